// round 8
// baseline (speedup 1.0000x reference)
#include <cuda_runtime.h>
#include <math.h>

#define B_ 4
#define N_ 1024
#define C_ 768
#define H_ 12
#define DH 64
#define QT 16
#define TOPK 128

#define OUT0 (B_*N_*C_)

typedef unsigned long long ull;

// ---------------- scratch ----------------
__device__ float g_q[B_*H_*N_*DH];
__device__ float g_kT[B_*H_*DH*N_];   // [b][h][d][n]
__device__ float g_v[B_*H_*N_*DH];
__device__ float g_ctx[B_*H_*N_*DH];

// ---------------- helpers ----------------
__device__ __forceinline__ void ffma2(ull& d, ull a, ull b) {
    asm("fma.rn.f32x2 %0, %1, %2, %0;" : "+l"(d) : "l"(a), "l"(b));
}
__device__ __forceinline__ ull splat(float f) {
    ull r; asm("mov.b64 %0, {%1,%1};" : "=l"(r) : "f"(f)); return r;
}
__device__ __forceinline__ float2 u2f(ull v) {
    float2 r; asm("mov.b64 {%0,%1}, %2;" : "=f"(r.x), "=f"(r.y) : "l"(v)); return r;
}
__device__ __forceinline__ unsigned fkey(float f) {
    unsigned u = __float_as_uint(f);
    return (u & 0x80000000u) ? ~u : (u | 0x80000000u);
}
// inverse of fkey (monotone bijection), for float-domain compares
__device__ __forceinline__ float finv(unsigned u) {
    unsigned b = (u & 0x80000000u) ? (u & 0x7fffffffu) : ~u;
    return __uint_as_float(b);
}
__device__ __forceinline__ float wredsum(float v) {
    #pragma unroll
    for (int o = 16; o; o >>= 1) v += __shfl_xor_sync(0xffffffffu, v, o);
    return v;
}
__device__ __forceinline__ float wredmax(float v) {
    #pragma unroll
    for (int o = 16; o; o >>= 1) v = fmaxf(v, __shfl_xor_sync(0xffffffffu, v, o));
    return v;
}

#define AS 132

// ======================= 128x128x16 FFMA2 GEMM core =======================
__device__ __forceinline__ void gemm_tile(const float* As, const float* Bs,
                                          int tm, int to, ull acc[8][4])
{
    #pragma unroll
    for (int kk = 0; kk < 16; kk++) {
        float4 a0 = *(const float4*)&As[kk*AS + tm*4];
        float4 a1 = *(const float4*)&As[kk*AS + tm*4 + 64];
        ulonglong2 b0 = *(const ulonglong2*)&Bs[kk*AS + to*4];
        ulonglong2 b1 = *(const ulonglong2*)&Bs[kk*AS + to*4 + 64];
        ull as_[8];
        as_[0] = splat(a0.x); as_[1] = splat(a0.y);
        as_[2] = splat(a0.z); as_[3] = splat(a0.w);
        as_[4] = splat(a1.x); as_[5] = splat(a1.y);
        as_[6] = splat(a1.z); as_[7] = splat(a1.w);
        #pragma unroll
        for (int r = 0; r < 8; r++) {
            ffma2(acc[r][0], as_[r], b0.x);
            ffma2(acc[r][1], as_[r], b0.y);
            ffma2(acc[r][2], as_[r], b1.x);
            ffma2(acc[r][3], as_[r], b1.y);
        }
    }
}

__device__ __forceinline__ void stage_frag(float* As, float* Bs, int lrow, int lc4,
                                           const float4 fa[2], const float4 fb[2])
{
    #pragma unroll
    for (int it = 0; it < 2; it++) {
        int row = it*64 + lrow;
        As[(lc4+0)*AS + row] = fa[it].x;
        As[(lc4+1)*AS + row] = fa[it].y;
        As[(lc4+2)*AS + row] = fa[it].z;
        As[(lc4+3)*AS + row] = fa[it].w;
        Bs[(lc4+0)*AS + row] = fb[it].x;
        Bs[(lc4+1)*AS + row] = fb[it].y;
        Bs[(lc4+2)*AS + row] = fb[it].z;
        Bs[(lc4+3)*AS + row] = fb[it].w;
    }
}

// ---------------- QKV GEMM (double-buffered) ----------------
__global__ __launch_bounds__(256, 2) void qkv_gemm(const float* __restrict__ X,
                                                   const float* __restrict__ W)
{
    __shared__ float As[2][16*AS];
    __shared__ float Bs[2][16*AS];
    const int m0 = blockIdx.y * 128;
    const int o0 = blockIdx.x * 128;
    const int tid  = threadIdx.x;
    const int lrow = tid >> 2;
    const int lc4  = (tid & 3) << 2;
    const int tm = tid >> 4;
    const int to = tid & 15;

    ull acc[8][4];
    #pragma unroll
    for (int r = 0; r < 8; r++)
        #pragma unroll
        for (int c = 0; c < 4; c++) acc[r][c] = 0ull;

    float4 fa[2], fb[2];
    #pragma unroll
    for (int it = 0; it < 2; it++) {
        fa[it] = *(const float4*)&X[(m0 + it*64 + lrow) * C_ + lc4];
        fb[it] = *(const float4*)&W[(o0 + it*64 + lrow) * C_ + lc4];
    }
    stage_frag(As[0], Bs[0], lrow, lc4, fa, fb);
    __syncthreads();
    int p = 0;
    for (int k0 = 0; k0 < C_; k0 += 16) {
        if (k0 + 16 < C_) {
            #pragma unroll
            for (int it = 0; it < 2; it++) {
                fa[it] = *(const float4*)&X[(m0 + it*64 + lrow) * C_ + k0 + 16 + lc4];
                fb[it] = *(const float4*)&W[(o0 + it*64 + lrow) * C_ + k0 + 16 + lc4];
            }
        }
        gemm_tile(As[p], Bs[p], tm, to, acc);
        if (k0 + 16 < C_) {
            stage_frag(As[p^1], Bs[p^1], lrow, lc4, fa, fb);
            __syncthreads();
            p ^= 1;
        }
    }

    const int part = o0 / C_;
    const int h0   = (o0 % C_) / DH;
    const int b    = m0 >> 10;
    const int n0   = m0 & 1023;
    const int d4   = to * 4;

    if (part == 1) {
        float* kt  = g_kT + ((b * H_ + h0) * DH) * N_;
        float* kt1 = kt + DH * N_;
        #pragma unroll
        for (int rg = 0; rg < 2; rg++)
            #pragma unroll
            for (int i = 0; i < 4; i++) {
                int n = n0 + rg*64 + tm*4 + i;
                int r = rg*4 + i;
                float2 v0 = u2f(acc[r][0]), v1 = u2f(acc[r][1]);
                float2 v2 = u2f(acc[r][2]), v3 = u2f(acc[r][3]);
                kt [(d4+0)*N_ + n] = v0.x; kt [(d4+1)*N_ + n] = v0.y;
                kt [(d4+2)*N_ + n] = v1.x; kt [(d4+3)*N_ + n] = v1.y;
                kt1[(d4+0)*N_ + n] = v2.x; kt1[(d4+1)*N_ + n] = v2.y;
                kt1[(d4+2)*N_ + n] = v3.x; kt1[(d4+3)*N_ + n] = v3.y;
            }
    } else {
        float* dst = (part == 0) ? g_q : g_v;
        float* d0 = dst + ((b * H_ + h0)     * N_) * DH;
        float* d1 = dst + ((b * H_ + h0 + 1) * N_) * DH;
        #pragma unroll
        for (int rg = 0; rg < 2; rg++)
            #pragma unroll
            for (int i = 0; i < 4; i++) {
                int n = n0 + rg*64 + tm*4 + i;
                int r = rg*4 + i;
                float2 v0 = u2f(acc[r][0]), v1 = u2f(acc[r][1]);
                float2 v2 = u2f(acc[r][2]), v3 = u2f(acc[r][3]);
                *(float4*)&d0[n*DH + d4] = make_float4(v0.x, v0.y, v1.x, v1.y);
                *(float4*)&d1[n*DH + d4] = make_float4(v2.x, v2.y, v3.x, v3.y);
            }
    }
}

// ---------------- Proj GEMM (double-buffered) ----------------
__global__ __launch_bounds__(256, 2) void proj_gemm(const float* __restrict__ W,
                                                    const float* __restrict__ bias,
                                                    float* __restrict__ out)
{
    __shared__ float As[2][16*AS];
    __shared__ float Bs[2][16*AS];
    const int m0 = blockIdx.y * 128;
    const int o0 = blockIdx.x * 128;
    const int tid  = threadIdx.x;
    const int lrow = tid >> 2;
    const int lc4  = (tid & 3) << 2;
    const int tm = tid >> 4;
    const int to = tid & 15;

    ull acc[8][4];
    #pragma unroll
    for (int r = 0; r < 8; r++)
        #pragma unroll
        for (int c = 0; c < 4; c++) acc[r][c] = 0ull;

    float4 fa[2], fb[2];
    #pragma unroll
    for (int it = 0; it < 2; it++) {
        int m = m0 + it*64 + lrow;
        int bb = m >> 10, n = m & 1023;
        int h = lc4 >> 6, d = lc4 & 63;
        fa[it] = *(const float4*)&g_ctx[(((bb * H_ + h) * N_) + n) * DH + d];
        fb[it] = *(const float4*)&W[(o0 + it*64 + lrow) * C_ + lc4];
    }
    stage_frag(As[0], Bs[0], lrow, lc4, fa, fb);
    __syncthreads();
    int p = 0;
    for (int k0 = 0; k0 < C_; k0 += 16) {
        if (k0 + 16 < C_) {
            int k = k0 + 16 + lc4;
            int h = k >> 6, d = k & 63;
            #pragma unroll
            for (int it = 0; it < 2; it++) {
                int m = m0 + it*64 + lrow;
                int bb = m >> 10, n = m & 1023;
                fa[it] = *(const float4*)&g_ctx[(((bb * H_ + h) * N_) + n) * DH + d];
                fb[it] = *(const float4*)&W[(o0 + it*64 + lrow) * C_ + k0 + 16 + lc4];
            }
        }
        gemm_tile(As[p], Bs[p], tm, to, acc);
        if (k0 + 16 < C_) {
            stage_frag(As[p^1], Bs[p^1], lrow, lc4, fa, fb);
            __syncthreads();
            p ^= 1;
        }
    }

    float4 bs0 = *(const float4*)&bias[o0 + to*4];
    float4 bs1 = *(const float4*)&bias[o0 + 64 + to*4];
    #pragma unroll
    for (int rg = 0; rg < 2; rg++)
        #pragma unroll
        for (int i = 0; i < 4; i++) {
            int mo = m0 + rg*64 + tm*4 + i;
            int r = rg*4 + i;
            float2 v0 = u2f(acc[r][0]), v1 = u2f(acc[r][1]);
            float2 v2 = u2f(acc[r][2]), v3 = u2f(acc[r][3]);
            *(float4*)&out[mo * C_ + o0 + to*4] =
                make_float4(v0.x + bs0.x, v0.y + bs0.y, v1.x + bs0.z, v1.y + bs0.w);
            *(float4*)&out[mo * C_ + o0 + 64 + to*4] =
                make_float4(v2.x + bs1.x, v2.y + bs1.y, v3.x + bs1.z, v3.y + bs1.w);
        }
}

// ---------------- Attention core ----------------
// smem: sQ2 8K | sS 64K | sExpl 64K | wl 8K | idxl 4K | mcnt 16K = 164KB
#define SM_Q2   0
#define SM_S    (8192)
#define SM_EXPL (8192 + 65536)
#define SM_WL   (8192 + 65536 + 65536)
#define SM_IDX  (SM_WL + 8192)
#define SM_MC   (SM_IDX + 4096)
#define SMEM_ATTN (SM_MC + 16384)

__global__ __launch_bounds__(512, 1) void attn_kernel(const float* __restrict__ cnt,
                                                      const int* __restrict__ counter_p,
                                                      float* __restrict__ sd)
{
    extern __shared__ char smem[];
    float2*         sQ2   = (float2*)(smem + SM_Q2);
    float*          sS    = (float*)(smem + SM_S);
    float*          sExpl = (float*)(smem + SM_EXPL);
    float*          wl    = (float*)(smem + SM_WL);
    unsigned short* idxl  = (unsigned short*)(smem + SM_IDX);
    unsigned char*  mcnt  = (unsigned char*)(smem + SM_MC);

    const int h    = blockIdx.y;
    const int q0   = blockIdx.x * QT;
    const int tid  = threadIdx.x;
    const int lane = tid & 31;
    const int w    = tid >> 5;
    const float logc = logf((float)(*counter_p) + 1.0f);

    for (int i = tid; i < QT*N_/4; i += 512) ((unsigned*)mcnt)[i] = 0u;

    // exploration bonus, once per block (batch-independent)
    for (int i = tid; i < QT*N_/4; i += 512) {
        int r  = i >> 8;
        int j4 = (i & 255) << 2;
        float4 c = *(const float4*)&cnt[(h*N_ + q0 + r)*N_ + j4];
        float4 e;
        e.x = sqrtf(logc / (c.x + 1e-6f));
        e.y = sqrtf(logc / (c.y + 1e-6f));
        e.z = sqrtf(logc / (c.z + 1e-6f));
        e.w = sqrtf(logc / (c.w + 1e-6f));
        *(float4*)&sExpl[r*N_ + j4] = e;
    }

    for (int b = 0; b < B_; b++) {
        const float* KT = g_kT + ((b*H_ + h) * DH) * N_;
        const float* Vb = g_v  + ((b*H_ + h) * N_) * DH;
        __syncthreads();
        for (int i = tid; i < QT*DH; i += 512) {
            int r = i >> 6, kk = i & 63;
            float qv = g_q[((b*H_ + h)*N_ + q0 + r)*DH + kk] * 0.125f;
            sQ2[r*DH + kk] = make_float2(qv, qv);
        }
        __syncthreads();

        // ---- score GEMM ----
        {
            const int rg = (w & 1) * 8;
            const int jb = (w >> 1) * 128 + 4 * lane;
            ull acc[8][2];
            #pragma unroll
            for (int r = 0; r < 8; r++) { acc[r][0] = 0ull; acc[r][1] = 0ull; }
            #pragma unroll 4
            for (int kk = 0; kk < DH; kk += 2) {
                ulonglong2 kA = *(const ulonglong2*)&KT[kk*N_ + jb];
                ulonglong2 kB = *(const ulonglong2*)&KT[(kk+1)*N_ + jb];
                #pragma unroll
                for (int r = 0; r < 8; r++) {
                    ulonglong2 q2 = *(const ulonglong2*)&sQ2[(rg + r)*DH + kk];
                    ffma2(acc[r][0], q2.x, kA.x);
                    ffma2(acc[r][1], q2.x, kA.y);
                    ffma2(acc[r][0], q2.y, kB.x);
                    ffma2(acc[r][1], q2.y, kB.y);
                }
            }
            #pragma unroll
            for (int r = 0; r < 8; r++) {
                float2 v0 = u2f(acc[r][0]), v1 = u2f(acc[r][1]);
                *(float4*)&sS[(rg + r)*N_ + jb] = make_float4(v0.x, v0.y, v1.x, v1.y);
            }
        }
        __syncthreads();

        // ---- selection + context: warp w owns row r = w ----
        {
            const int r = w;
            const float* srow = &sS[r*N_];
            const float* erow = &sExpl[r*N_];
            // keys: u<16 as sortable uints (ALU), u>=16 as floats (FMA pipe)
            unsigned ukey[16];
            float    fval[16];
            float m = -1e30f;
            #pragma unroll
            for (int u4 = 0; u4 < 8; u4++) {
                float4 sv = *(const float4*)&srow[u4*128 + 4*lane];
                float4 ev = *(const float4*)&erow[u4*128 + 4*lane];
                float k0 = sv.x + ev.x, k1 = sv.y + ev.y;
                float k2 = sv.z + ev.z, k3 = sv.w + ev.w;
                if (u4 < 4) {
                    ukey[u4*4+0] = fkey(k0); ukey[u4*4+1] = fkey(k1);
                    ukey[u4*4+2] = fkey(k2); ukey[u4*4+3] = fkey(k3);
                } else {
                    fval[(u4-4)*4+0] = k0; fval[(u4-4)*4+1] = k1;
                    fval[(u4-4)*4+2] = k2; fval[(u4-4)*4+3] = k3;
                }
                m = fmaxf(m, fmaxf(fmaxf(sv.x, sv.y), fmaxf(sv.z, sv.w)));
            }
            m = wredmax(m);
            // full softmax denominator
            float z = 0.f;
            #pragma unroll
            for (int u4 = 0; u4 < 8; u4++) {
                float4 sv = *(const float4*)&srow[u4*128 + 4*lane];
                z += __expf(sv.x - m) + __expf(sv.y - m)
                   + __expf(sv.z - m) + __expf(sv.w - m);
            }
            z = wredsum(z);

            // exact top-128 threshold: pipe-balanced bisection
            unsigned T = 0;
            for (int bit = 31; bit >= 0; bit--) {
                unsigned Tc = T | (1u << bit);
                float vT = finv(Tc);
                int ci = 0; float cf = 0.f;
                #pragma unroll
                for (int u = 0; u < 16; u++) if (ukey[u] >= Tc) ci++;
                #pragma unroll
                for (int u = 0; u < 16; u++) if (fval[u] >= vT) cf += 1.f;
                int c = __reduce_add_sync(0xffffffffu, ci + __float2int_rn(cf));
                if (c >= TOPK) T = Tc;
                if (c == TOPK) break;
            }
            const float vTf = finv(T);

            // compaction
            int base = 0;
            float esum = 0.f;
            const unsigned lmask = (1u << lane) - 1u;
            #pragma unroll
            for (int u = 0; u < 32; u++) {
                bool sel = (u < 16) ? (ukey[u] >= T) : (fval[u-16] >= vTf);
                unsigned bal = __ballot_sync(0xffffffffu, sel);
                if (sel) {
                    int pos = base + __popc(bal & lmask);
                    if (pos < TOPK) {
                        int j = (u >> 2)*128 + 4*lane + (u & 3);
                        float e = __expf(srow[j] - m);
                        esum += e;
                        idxl[r*TOPK + pos] = (unsigned short)j;
                        wl[r*TOPK + pos]   = e;
                        mcnt[r*N_ + j] = (unsigned char)(mcnt[r*N_ + j] + 1);
                    }
                }
                base += __popc(bal);
            }
            esum = wredsum(esum);
            float inv = 1.f / (esum + 1e-8f * z);
            for (int i = lane; i < TOPK; i += 32) wl[r*TOPK + i] *= inv;
            __syncwarp();

            // sparse context
            float2 a = make_float2(0.f, 0.f);
            #pragma unroll 4
            for (int i = 0; i < TOPK; i++) {
                int   j  = idxl[r*TOPK + i];
                float ww = wl[r*TOPK + i];
                float2 v2 = *(const float2*)&Vb[j*DH + 2*lane];
                a.x += ww * v2.x;
                a.y += ww * v2.y;
            }
            *(float2*)&g_ctx[((b*H_ + h)*N_ + q0 + r)*DH + 2*lane] = a;
        }
    }
    __syncthreads();

    for (int i = tid; i < QT*N_/4; i += 512) {
        int r  = i >> 8;
        int j4 = i & 255;
        unsigned mv = ((const unsigned*)mcnt)[r*256 + j4];
        float4 o;
        o.x = (float)( mv        & 255u);
        o.y = (float)((mv >>  8) & 255u);
        o.z = (float)((mv >> 16) & 255u);
        o.w = (float)((mv >> 24) & 255u);
        *(float4*)&sd[(h*N_ + q0 + r)*N_ + (j4 << 2)] = o;
    }
}

// ---------------- launch ----------------
extern "C" void kernel_launch(void* const* d_in, const int* in_sizes, int n_in,
                              void* d_out, int out_size)
{
    const float* x     = (const float*)d_in[0];
    const float* qkvw  = (const float*)d_in[1];
    const float* projw = (const float*)d_in[2];
    const float* projb = (const float*)d_in[3];
    const float* ucb   = (const float*)d_in[4];
    const int*   ctr   = (const int*)d_in[5];
    float* out = (float*)d_out;
    float* sd  = out + OUT0;

    cudaFuncSetAttribute(attn_kernel, cudaFuncAttributeMaxDynamicSharedMemorySize, SMEM_ATTN);

    qkv_gemm<<<dim3(18, 32), 256>>>(x, qkvw);
    attn_kernel<<<dim3(64, 12), 512, SMEM_ATTN>>>(ucb, ctr, sd);
    proj_gemm<<<dim3(6, 32), 256>>>(projw, projb, out);
}

// round 9
// speedup vs baseline: 1.5438x; 1.5438x over previous
#include <cuda_runtime.h>
#include <math.h>

#define B_ 4
#define N_ 1024
#define C_ 768
#define H_ 12
#define DH 64
#define QT 16
#define TOPK 128

#define OUT0 (B_*N_*C_)

typedef unsigned long long ull;

// ---------------- scratch ----------------
__device__ float g_q[B_*H_*N_*DH];    // pre-scaled by 0.125
__device__ float g_kT[B_*H_*DH*N_];   // [b][h][d][n]
__device__ float g_v[B_*H_*N_*DH];
__device__ float g_ctx[B_*H_*N_*DH];

// ---------------- helpers ----------------
__device__ __forceinline__ void ffma2(ull& d, ull a, ull b) {
    asm("fma.rn.f32x2 %0, %1, %2, %0;" : "+l"(d) : "l"(a), "l"(b));
}
__device__ __forceinline__ ull splat(float f) {
    ull r; asm("mov.b64 %0, {%1,%1};" : "=l"(r) : "f"(f)); return r;
}
__device__ __forceinline__ float2 u2f(ull v) {
    float2 r; asm("mov.b64 {%0,%1}, %2;" : "=f"(r.x), "=f"(r.y) : "l"(v)); return r;
}
__device__ __forceinline__ unsigned fkey(float f) {
    unsigned u = __float_as_uint(f);
    return (u & 0x80000000u) ? ~u : (u | 0x80000000u);
}
__device__ __forceinline__ float wredsum(float v) {
    #pragma unroll
    for (int o = 16; o; o >>= 1) v += __shfl_xor_sync(0xffffffffu, v, o);
    return v;
}
__device__ __forceinline__ float wredmax(float v) {
    #pragma unroll
    for (int o = 16; o; o >>= 1) v = fmaxf(v, __shfl_xor_sync(0xffffffffu, v, o));
    return v;
}

#define AS 132

// ======================= 128x128x16 FFMA2 GEMM core (round-4) =============
__device__ __forceinline__ void gemm_tile(const float* As, const float* Bs,
                                          int tm, int to, ull acc[8][4])
{
    #pragma unroll
    for (int kk = 0; kk < 16; kk++) {
        float4 a0 = *(const float4*)&As[kk*AS + tm*4];
        float4 a1 = *(const float4*)&As[kk*AS + tm*4 + 64];
        ulonglong2 b0 = *(const ulonglong2*)&Bs[kk*AS + to*4];
        ulonglong2 b1 = *(const ulonglong2*)&Bs[kk*AS + to*4 + 64];
        ull as_[8];
        as_[0] = splat(a0.x); as_[1] = splat(a0.y);
        as_[2] = splat(a0.z); as_[3] = splat(a0.w);
        as_[4] = splat(a1.x); as_[5] = splat(a1.y);
        as_[6] = splat(a1.z); as_[7] = splat(a1.w);
        #pragma unroll
        for (int r = 0; r < 8; r++) {
            ffma2(acc[r][0], as_[r], b0.x);
            ffma2(acc[r][1], as_[r], b0.y);
            ffma2(acc[r][2], as_[r], b1.x);
            ffma2(acc[r][3], as_[r], b1.y);
        }
    }
}

__device__ __forceinline__ void stage_frag(float* As, float* Bs, int lrow, int lc4,
                                           const float4 fa[2], const float4 fb[2])
{
    #pragma unroll
    for (int it = 0; it < 2; it++) {
        int row = it*64 + lrow;
        As[(lc4+0)*AS + row] = fa[it].x;
        As[(lc4+1)*AS + row] = fa[it].y;
        As[(lc4+2)*AS + row] = fa[it].z;
        As[(lc4+3)*AS + row] = fa[it].w;
        Bs[(lc4+0)*AS + row] = fb[it].x;
        Bs[(lc4+1)*AS + row] = fb[it].y;
        Bs[(lc4+2)*AS + row] = fb[it].z;
        Bs[(lc4+3)*AS + row] = fb[it].w;
    }
}

// ---------------- QKV GEMM (round-4, single buffer) ----------------
__global__ __launch_bounds__(256, 2) void qkv_gemm(const float* __restrict__ X,
                                                   const float* __restrict__ W)
{
    __shared__ float As[16*AS];
    __shared__ float Bs[16*AS];
    const int m0 = blockIdx.y * 128;
    const int o0 = blockIdx.x * 128;
    const int tid  = threadIdx.x;
    const int lrow = tid >> 2;
    const int lc4  = (tid & 3) << 2;
    const int tm = tid >> 4;
    const int to = tid & 15;

    ull acc[8][4];
    #pragma unroll
    for (int r = 0; r < 8; r++)
        #pragma unroll
        for (int c = 0; c < 4; c++) acc[r][c] = 0ull;

    float4 fa[2], fb[2];
    #pragma unroll
    for (int it = 0; it < 2; it++) {
        fa[it] = *(const float4*)&X[(m0 + it*64 + lrow) * C_ + lc4];
        fb[it] = *(const float4*)&W[(o0 + it*64 + lrow) * C_ + lc4];
    }
    for (int k0 = 0; k0 < C_; k0 += 16) {
        __syncthreads();
        stage_frag(As, Bs, lrow, lc4, fa, fb);
        __syncthreads();
        if (k0 + 16 < C_) {
            #pragma unroll
            for (int it = 0; it < 2; it++) {
                fa[it] = *(const float4*)&X[(m0 + it*64 + lrow) * C_ + k0 + 16 + lc4];
                fb[it] = *(const float4*)&W[(o0 + it*64 + lrow) * C_ + k0 + 16 + lc4];
            }
        }
        gemm_tile(As, Bs, tm, to, acc);
    }

    const int part = o0 / C_;
    const int h0   = (o0 % C_) / DH;
    const int b    = m0 >> 10;
    const int n0   = m0 & 1023;
    const int d4   = to * 4;

    if (part == 1) {
        float* kt  = g_kT + ((b * H_ + h0) * DH) * N_;
        float* kt1 = kt + DH * N_;
        #pragma unroll
        for (int rg = 0; rg < 2; rg++)
            #pragma unroll
            for (int i = 0; i < 4; i++) {
                int n = n0 + rg*64 + tm*4 + i;
                int r = rg*4 + i;
                float2 v0 = u2f(acc[r][0]), v1 = u2f(acc[r][1]);
                float2 v2 = u2f(acc[r][2]), v3 = u2f(acc[r][3]);
                kt [(d4+0)*N_ + n] = v0.x; kt [(d4+1)*N_ + n] = v0.y;
                kt [(d4+2)*N_ + n] = v1.x; kt [(d4+3)*N_ + n] = v1.y;
                kt1[(d4+0)*N_ + n] = v2.x; kt1[(d4+1)*N_ + n] = v2.y;
                kt1[(d4+2)*N_ + n] = v3.x; kt1[(d4+3)*N_ + n] = v3.y;
            }
    } else {
        const bool isq = (part == 0);
        const float sc = isq ? 0.125f : 1.0f;   // fold q scaling here
        float* dst = isq ? g_q : g_v;
        float* d0 = dst + ((b * H_ + h0)     * N_) * DH;
        float* d1 = dst + ((b * H_ + h0 + 1) * N_) * DH;
        #pragma unroll
        for (int rg = 0; rg < 2; rg++)
            #pragma unroll
            for (int i = 0; i < 4; i++) {
                int n = n0 + rg*64 + tm*4 + i;
                int r = rg*4 + i;
                float2 v0 = u2f(acc[r][0]), v1 = u2f(acc[r][1]);
                float2 v2 = u2f(acc[r][2]), v3 = u2f(acc[r][3]);
                *(float4*)&d0[n*DH + d4] =
                    make_float4(v0.x*sc, v0.y*sc, v1.x*sc, v1.y*sc);
                *(float4*)&d1[n*DH + d4] =
                    make_float4(v2.x*sc, v2.y*sc, v3.x*sc, v3.y*sc);
            }
    }
}

// ---------------- Proj GEMM: 128(m) x 64(o) tiles ----------------
#define BS2 68
__global__ __launch_bounds__(256, 2) void proj_gemm(const float* __restrict__ W,
                                                    const float* __restrict__ bias,
                                                    float* __restrict__ out)
{
    __shared__ float As[16*AS];
    __shared__ float Bs[16*BS2];
    const int m0 = blockIdx.y * 128;
    const int o0 = blockIdx.x * 64;
    const int tid  = threadIdx.x;
    const int lrow = tid >> 2;            // 0..63
    const int lc4  = (tid & 3) << 2;
    const int tm = tid >> 4;
    const int to = tid & 15;

    ull acc[8][2];
    #pragma unroll
    for (int r = 0; r < 8; r++) { acc[r][0] = 0ull; acc[r][1] = 0ull; }

    float4 fa[2], fb;
    #pragma unroll
    for (int it = 0; it < 2; it++) {
        int m = m0 + it*64 + lrow;
        int bb = m >> 10, n = m & 1023;
        int h = lc4 >> 6, d = lc4 & 63;
        fa[it] = *(const float4*)&g_ctx[(((bb * H_ + h) * N_) + n) * DH + d];
    }
    fb = *(const float4*)&W[(o0 + lrow) * C_ + lc4];  // lrow 0..63 covers 64 o-rows

    for (int k0 = 0; k0 < C_; k0 += 16) {
        __syncthreads();
        #pragma unroll
        for (int it = 0; it < 2; it++) {
            int row = it*64 + lrow;
            As[(lc4+0)*AS + row] = fa[it].x;
            As[(lc4+1)*AS + row] = fa[it].y;
            As[(lc4+2)*AS + row] = fa[it].z;
            As[(lc4+3)*AS + row] = fa[it].w;
        }
        Bs[(lc4+0)*BS2 + lrow] = fb.x;
        Bs[(lc4+1)*BS2 + lrow] = fb.y;
        Bs[(lc4+2)*BS2 + lrow] = fb.z;
        Bs[(lc4+3)*BS2 + lrow] = fb.w;
        __syncthreads();
        if (k0 + 16 < C_) {
            int k = k0 + 16 + lc4;
            int h = k >> 6, d = k & 63;
            #pragma unroll
            for (int it = 0; it < 2; it++) {
                int m = m0 + it*64 + lrow;
                int bb = m >> 10, n = m & 1023;
                fa[it] = *(const float4*)&g_ctx[(((bb * H_ + h) * N_) + n) * DH + d];
            }
            fb = *(const float4*)&W[(o0 + lrow) * C_ + k0 + 16 + lc4];
        }
        #pragma unroll
        for (int kk = 0; kk < 16; kk++) {
            float4 a0 = *(const float4*)&As[kk*AS + tm*4];
            float4 a1 = *(const float4*)&As[kk*AS + tm*4 + 64];
            ulonglong2 b0 = *(const ulonglong2*)&Bs[kk*BS2 + to*4];
            ull as_[8];
            as_[0] = splat(a0.x); as_[1] = splat(a0.y);
            as_[2] = splat(a0.z); as_[3] = splat(a0.w);
            as_[4] = splat(a1.x); as_[5] = splat(a1.y);
            as_[6] = splat(a1.z); as_[7] = splat(a1.w);
            #pragma unroll
            for (int r = 0; r < 8; r++) {
                ffma2(acc[r][0], as_[r], b0.x);
                ffma2(acc[r][1], as_[r], b0.y);
            }
        }
    }

    float4 bs0 = *(const float4*)&bias[o0 + to*4];
    #pragma unroll
    for (int rg = 0; rg < 2; rg++)
        #pragma unroll
        for (int i = 0; i < 4; i++) {
            int mo = m0 + rg*64 + tm*4 + i;
            int r = rg*4 + i;
            float2 v0 = u2f(acc[r][0]), v1 = u2f(acc[r][1]);
            *(float4*)&out[mo * C_ + o0 + to*4] =
                make_float4(v0.x + bs0.x, v0.y + bs0.y, v1.x + bs0.z, v1.y + bs0.w);
        }
}

// ---------------- Attention core (round-4 + expl hoist + Q preload) -------
// smem: sQ2 32K | sS 64K | sExpl 64K | wl 8K | idxl 4K | mcnt 16K = 188KB
#define SM_Q2   0
#define SM_S    (32768)
#define SM_EXPL (32768 + 65536)
#define SM_WL   (SM_EXPL + 65536)
#define SM_IDX  (SM_WL + 8192)
#define SM_MC   (SM_IDX + 4096)
#define SMEM_ATTN (SM_MC + 16384)

__global__ __launch_bounds__(512, 1) void attn_kernel(const float* __restrict__ cnt,
                                                      const int* __restrict__ counter_p,
                                                      float* __restrict__ sd)
{
    extern __shared__ char smem[];
    float2*         sQ2   = (float2*)(smem + SM_Q2);     // [4][16][64]
    float*          sS    = (float*)(smem + SM_S);       // [16][1024]
    float*          sExpl = (float*)(smem + SM_EXPL);    // [16][1024]
    float*          wl    = (float*)(smem + SM_WL);
    unsigned short* idxl  = (unsigned short*)(smem + SM_IDX);
    unsigned char*  mcnt  = (unsigned char*)(smem + SM_MC);

    const int h    = blockIdx.y;
    const int q0   = blockIdx.x * QT;
    const int tid  = threadIdx.x;
    const int lane = tid & 31;
    const int w    = tid >> 5;
    const float logc = logf((float)(*counter_p) + 1.0f);

    for (int i = tid; i < QT*N_/4; i += 512) ((unsigned*)mcnt)[i] = 0u;

    // Q for all batches, once (already scaled by 0.125 in qkv epilogue)
    for (int i = tid; i < B_*QT*DH; i += 512) {
        int b = i >> 10, r = (i >> 6) & 15, kk = i & 63;
        float qv = g_q[((b*H_ + h)*N_ + q0 + r)*DH + kk];
        sQ2[(b*QT + r)*DH + kk] = make_float2(qv, qv);
    }
    // exploration bonus, once (batch-independent)
    for (int i = tid; i < QT*N_/4; i += 512) {
        int r  = i >> 8;
        int j4 = (i & 255) << 2;
        float4 c = *(const float4*)&cnt[(h*N_ + q0 + r)*N_ + j4];
        float4 e;
        e.x = sqrtf(logc / (c.x + 1e-6f));
        e.y = sqrtf(logc / (c.y + 1e-6f));
        e.z = sqrtf(logc / (c.z + 1e-6f));
        e.w = sqrtf(logc / (c.w + 1e-6f));
        *(float4*)&sExpl[r*N_ + j4] = e;
    }

    for (int b = 0; b < B_; b++) {
        const float* KT = g_kT + ((b*H_ + h) * DH) * N_;
        const float* Vb = g_v  + ((b*H_ + h) * N_) * DH;
        __syncthreads();   // prev selection done reading sS / first-iter staging done

        // ---- score GEMM ----
        {
            const int rg = (w & 1) * 8;
            const int jb = (w >> 1) * 128 + 4 * lane;
            ull acc[8][2];
            #pragma unroll
            for (int r = 0; r < 8; r++) { acc[r][0] = 0ull; acc[r][1] = 0ull; }
            #pragma unroll 4
            for (int kk = 0; kk < DH; kk += 2) {
                ulonglong2 kA = *(const ulonglong2*)&KT[kk*N_ + jb];
                ulonglong2 kB = *(const ulonglong2*)&KT[(kk+1)*N_ + jb];
                #pragma unroll
                for (int r = 0; r < 8; r++) {
                    ulonglong2 q2 = *(const ulonglong2*)&sQ2[(b*QT + rg + r)*DH + kk];
                    ffma2(acc[r][0], q2.x, kA.x);
                    ffma2(acc[r][1], q2.x, kA.y);
                    ffma2(acc[r][0], q2.y, kB.x);
                    ffma2(acc[r][1], q2.y, kB.y);
                }
            }
            #pragma unroll
            for (int r = 0; r < 8; r++) {
                float2 v0 = u2f(acc[r][0]), v1 = u2f(acc[r][1]);
                *(float4*)&sS[(rg + r)*N_ + jb] = make_float4(v0.x, v0.y, v1.x, v1.y);
            }
        }
        __syncthreads();

        // ---- selection + context: warp w owns row r = w (round-4 code) ----
        {
            const int r = w;
            float sval[32];
            unsigned ukey[32];
            float m = -1e30f;
            #pragma unroll
            for (int u4 = 0; u4 < 8; u4++) {
                float4 sv = *(const float4*)&sS[r*N_ + u4*128 + 4*lane];
                float4 ev = *(const float4*)&sExpl[r*N_ + u4*128 + 4*lane];
                sval[u4*4+0] = sv.x; ukey[u4*4+0] = fkey(sv.x + ev.x);
                sval[u4*4+1] = sv.y; ukey[u4*4+1] = fkey(sv.y + ev.y);
                sval[u4*4+2] = sv.z; ukey[u4*4+2] = fkey(sv.z + ev.z);
                sval[u4*4+3] = sv.w; ukey[u4*4+3] = fkey(sv.w + ev.w);
                m = fmaxf(m, fmaxf(fmaxf(sv.x, sv.y), fmaxf(sv.z, sv.w)));
            }
            m = wredmax(m);
            float z = 0.f;
            #pragma unroll
            for (int u = 0; u < 32; u++) z += __expf(sval[u] - m);
            z = wredsum(z);

            unsigned T = 0;
            for (int bit = 31; bit >= 0; bit--) {
                unsigned Tc = T | (1u << bit);
                int c = 0;
                #pragma unroll
                for (int u = 0; u < 32; u++) c += (ukey[u] >= Tc) ? 1 : 0;
                c = __reduce_add_sync(0xffffffffu, c);
                if (c >= TOPK) T = Tc;
                if (c == TOPK) break;
            }

            int base = 0;
            float esum = 0.f;
            const unsigned lmask = (1u << lane) - 1u;
            #pragma unroll
            for (int u = 0; u < 32; u++) {
                bool sel = (ukey[u] >= T);
                unsigned bal = __ballot_sync(0xffffffffu, sel);
                if (sel) {
                    int pos = base + __popc(bal & lmask);
                    if (pos < TOPK) {
                        int j = (u >> 2)*128 + 4*lane + (u & 3);
                        float e = __expf(sval[u] - m);
                        esum += e;
                        idxl[r*TOPK + pos] = (unsigned short)j;
                        wl[r*TOPK + pos]   = e;
                        mcnt[r*N_ + j] = (unsigned char)(mcnt[r*N_ + j] + 1);
                    }
                }
                base += __popc(bal);
            }
            esum = wredsum(esum);
            float inv = 1.f / (esum + 1e-8f * z);
            for (int i = lane; i < TOPK; i += 32) wl[r*TOPK + i] *= inv;
            __syncwarp();

            float2 a = make_float2(0.f, 0.f);
            #pragma unroll 4
            for (int i = 0; i < TOPK; i++) {
                int   j  = idxl[r*TOPK + i];
                float ww = wl[r*TOPK + i];
                float2 v2 = *(const float2*)&Vb[j*DH + 2*lane];
                a.x += ww * v2.x;
                a.y += ww * v2.y;
            }
            *(float2*)&g_ctx[((b*H_ + h)*N_ + q0 + r)*DH + 2*lane] = a;
        }
    }
    __syncthreads();

    for (int i = tid; i < QT*N_/4; i += 512) {
        int r  = i >> 8;
        int j4 = i & 255;
        unsigned mv = ((const unsigned*)mcnt)[r*256 + j4];
        float4 o;
        o.x = (float)( mv        & 255u);
        o.y = (float)((mv >>  8) & 255u);
        o.z = (float)((mv >> 16) & 255u);
        o.w = (float)((mv >> 24) & 255u);
        *(float4*)&sd[(h*N_ + q0 + r)*N_ + (j4 << 2)] = o;
    }
}

// ---------------- launch ----------------
extern "C" void kernel_launch(void* const* d_in, const int* in_sizes, int n_in,
                              void* d_out, int out_size)
{
    const float* x     = (const float*)d_in[0];
    const float* qkvw  = (const float*)d_in[1];
    const float* projw = (const float*)d_in[2];
    const float* projb = (const float*)d_in[3];
    const float* ucb   = (const float*)d_in[4];
    const int*   ctr   = (const int*)d_in[5];
    float* out = (float*)d_out;
    float* sd  = out + OUT0;

    cudaFuncSetAttribute(attn_kernel, cudaFuncAttributeMaxDynamicSharedMemorySize, SMEM_ATTN);

    qkv_gemm<<<dim3(18, 32), 256>>>(x, qkvw);
    attn_kernel<<<dim3(64, 12), 512, SMEM_ATTN>>>(ucb, ctr, sd);
    proj_gemm<<<dim3(12, 32), 256>>>(projw, projb, out);
}